// round 4
// baseline (speedup 1.0000x reference)
#include <cuda_runtime.h>
#include <cstdint>

#define DEPTH    3
#define MARGIN   0.1f
#define BETA     0.5f
#define MAXN     16384          // max tokens (B*T); actual 2048
#define MAXWIDTH 262144         // max 2*V; actual 64000

// ---- device scratch (allocation-free; zero-initialized at module load) ----
__device__ int      g_hist[DEPTH * MAXWIDTH];   // restored to zero every call
__device__ int      g_hash[DEPTH * MAXN];
__device__ float    g_row_nll  [MAXN];
__device__ float    g_row_mask [MAXN];
__device__ float    g_row_basis[MAXN];
__device__ unsigned g_done;                     // reset to 0 by last block

// fast softplus for the bulk sum (MUFU EX2/LG2 path)
__device__ __forceinline__ float softplus_fast(float x) {
    float e = __expf(-fabsf(x));
    return fmaxf(x, 0.0f) + __logf(1.0f + e);
}
// precise softplus for the two per-row scalars feeding log()
__device__ __forceinline__ float softplus_precise(float x) {
    float e = expf(-fabsf(x));
    return fmaxf(x, 0.0f) + log1pf(e);
}

// ---------------- kernel 1: hash + bincount ----------------
__global__ void hash_kernel(const long long* __restrict__ inputs,
                            const long long* __restrict__ targets,
                            const long long* __restrict__ salts,
                            int N, long long width) {
    int n = blockIdx.x * blockDim.x + threadIdx.x;
    if (n >= N) return;
    long long combined = inputs[n] * 31337LL + targets[n] * 2654435769LL;
#pragma unroll
    for (int d = 0; d < DEPTH; d++) {
        long long h = (combined + salts[d]) % width;
        if (h < 0) h += width;
        int hi = (int)h;
        g_hash[d * MAXN + n] = hi;
        atomicAdd(&g_hist[d * MAXWIDTH + hi], 1);
    }
}

// ---------------- kernel 2: stream + fused epilogue + last-block finish ----
// One block per row. Streams V floats (the only pass over the big tensor),
// reduces sum-of-softplus; thread 0 computes full per-row loss terms.
// The last block to finish reduces all per-row terms to the scalar output,
// then restores the histogram to zero (atomicSub replay) and resets g_done.
__global__ void __launch_bounds__(256) row_kernel(const float* __restrict__ logits,
                                                  const long long* __restrict__ targets,
                                                  float* __restrict__ out,
                                                  int V, int vec_ok) {
    const int r = blockIdx.x;
    const int N = gridDim.x;
    const float* row = logits + (size_t)r * V;

    float acc = 0.0f;
    if (vec_ok) {
        const float4* row4 = reinterpret_cast<const float4*>(row);
        const int n4 = V >> 2;
#pragma unroll 4
        for (int i = threadIdx.x; i < n4; i += 256) {
            float4 v = row4[i];
            acc += softplus_fast(v.x);
            acc += softplus_fast(v.y);
            acc += softplus_fast(v.z);
            acc += softplus_fast(v.w);
        }
    } else {
        for (int i = threadIdx.x; i < V; i += 256)
            acc += softplus_fast(row[i]);
    }

    // block reduce
    __shared__ float warp_sums[8];
#pragma unroll
    for (int off = 16; off > 0; off >>= 1)
        acc += __shfl_xor_sync(0xFFFFFFFFu, acc, off);
    int lane = threadIdx.x & 31, wid = threadIdx.x >> 5;
    if (lane == 0) warp_sums[wid] = acc;
    __syncthreads();

    if (threadIdx.x == 0) {
        float S = 0.0f;
#pragma unroll
        for (int w = 0; w < 8; w++) S += warp_sums[w];

        long long t = targets[r];
        bool valid  = (t != -1);
        int ti = (t >= 0 && t < V) ? (int)t : 0;
        float spt = softplus_precise(row[ti]);
        float spi = softplus_precise(row[0]);

        float scale = fminf(1.0f / (S + 1e-6f), 1.0f);
        float rem   = fmaxf(1.0f - S * scale, 0.0f);
        float p_t   = spt * scale + ((t == 0) ? rem : 0.0f);
        float p_i   = spi * scale + rem;

        g_row_nll [r] = valid ? logf(fmaxf(p_t, 1e-10f)) : 0.0f;
        g_row_mask[r] = valid ? 1.0f : 0.0f;

        int c = 0x7fffffff;
#pragma unroll
        for (int d = 0; d < DEPTH; d++) {
            int h = g_hash[d * MAXN + r];
            c = min(c, g_hist[d * MAXWIDTH + h]);
        }
        float strength = tanhf((float)c * 0.1f);
        g_row_basis[r] = fmaxf(p_i - p_t + MARGIN, 0.0f) * strength;
    }

    // ---- last-block-done: final reduction + histogram cleanup ----
    __shared__ unsigned is_last;
    __threadfence();                       // make per-row writes visible
    __syncthreads();                       // all threads past their work
    if (threadIdx.x == 0)
        is_last = (atomicAdd(&g_done, 1u) == (unsigned)(N - 1));
    __syncthreads();
    if (!is_last) return;

    // fixed-order deterministic reduction over N rows
    float nll_sum = 0.0f, mask_sum = 0.0f, basis_sum = 0.0f;
    for (int n = threadIdx.x; n < N; n += 256) {
        nll_sum   += g_row_nll[n];
        mask_sum  += g_row_mask[n];
        basis_sum += g_row_basis[n];
    }
    __shared__ float s0[8], s1[8], s2[8];
#pragma unroll
    for (int off = 16; off > 0; off >>= 1) {
        nll_sum   += __shfl_xor_sync(0xFFFFFFFFu, nll_sum,   off);
        mask_sum  += __shfl_xor_sync(0xFFFFFFFFu, mask_sum,  off);
        basis_sum += __shfl_xor_sync(0xFFFFFFFFu, basis_sum, off);
    }
    if (lane == 0) { s0[wid] = nll_sum; s1[wid] = mask_sum; s2[wid] = basis_sum; }
    __syncthreads();
    if (threadIdx.x == 0) {
        float a = 0, b = 0, c = 0;
#pragma unroll
        for (int w = 0; w < 8; w++) { a += s0[w]; b += s1[w]; c += s2[w]; }
        out[0] = -a / fmaxf(b, 1.0f) + BETA * (c / (float)N);
    }

    // restore histogram to zero by replaying hashes (graph-replay safe)
    for (int i = threadIdx.x; i < DEPTH * N; i += 256) {
        int d = i / N, n = i - d * N;
        atomicSub(&g_hist[d * MAXWIDTH + g_hash[d * MAXN + n]], 1);
    }
    __syncthreads();
    if (threadIdx.x == 0) g_done = 0;      // reset for next replay
}

extern "C" void kernel_launch(void* const* d_in, const int* in_sizes, int n_in,
                              void* d_out, int out_size) {
    // Resolve pointers by element count (robust to metadata ordering):
    //   salts: size == DEPTH; logits: largest; targets then inputs (relative order).
    const float*     logits  = nullptr;
    const long long* salts   = nullptr;
    const long long* tok[2]  = {nullptr, nullptr};
    int ntok_arrays = 0;
    long long logits_size = 0;
    int N = 0;

    for (int i = 0; i < n_in; i++) {
        long long sz = in_sizes[i];
        if (sz == DEPTH) {
            salts = (const long long*)d_in[i];
        } else if (sz > 1000000) {
            logits = (const float*)d_in[i];
            logits_size = sz;
        } else {
            if (ntok_arrays < 2) tok[ntok_arrays] = (const long long*)d_in[i];
            ntok_arrays++;
            N = (int)sz;
        }
    }
    const long long* targets = tok[0];
    const long long* inputs  = tok[1];

    int V = (N > 0) ? (int)(logits_size / N) : 0;
    long long width = 2LL * V;
    float* out = (float*)d_out;

    int vec_ok = (((uintptr_t)logits & 15) == 0) && (V % 4 == 0);

    hash_kernel<<<(N + 255) / 256, 256>>>(inputs, targets, salts, N, width);
    row_kernel<<<N, 256>>>(logits, targets, out, V, vec_ok);
}

// round 5
// speedup vs baseline: 1.1788x; 1.1788x over previous
#include <cuda_runtime.h>
#include <cstdint>

#define DEPTH    3
#define MARGIN   0.1f
#define BETA     0.5f
#define MAXN     16384          // max tokens (B*T); actual 2048
#define MAXWIDTH 262144         // max 2*V; actual 64000

// ---- device scratch (allocation-free; zero-initialized at module load,
//      and restored to zero by final_kernel every invocation) ----
__device__ int   g_hist[DEPTH * MAXWIDTH];
__device__ int   g_hash[DEPTH * MAXN];
__device__ float g_row_nll  [MAXN];
__device__ float g_row_mask [MAXN];
__device__ float g_row_basis[MAXN];

// fast softplus for the bulk sum (MUFU EX2/LG2 path)
__device__ __forceinline__ float softplus_fast(float x) {
    float e = __expf(-fabsf(x));
    return fmaxf(x, 0.0f) + __logf(1.0f + e);
}
// precise softplus for the two per-row scalars feeding log()
__device__ __forceinline__ float softplus_precise(float x) {
    float e = expf(-fabsf(x));
    return fmaxf(x, 0.0f) + log1pf(e);
}

// ---------------- kernel 1: hash + bincount ----------------
// g_hist is guaranteed zero on entry (module load / previous final_kernel).
__global__ void hash_kernel(const long long* __restrict__ inputs,
                            const long long* __restrict__ targets,
                            const long long* __restrict__ salts,
                            int N, long long width) {
    int n = blockIdx.x * blockDim.x + threadIdx.x;
    if (n >= N) return;
    long long combined = inputs[n] * 31337LL + targets[n] * 2654435769LL;
#pragma unroll
    for (int d = 0; d < DEPTH; d++) {
        long long h = (combined + salts[d]) % width;
        if (h < 0) h += width;
        int hi = (int)h;
        g_hash[d * MAXN + n] = hi;
        atomicAdd(&g_hist[d * MAXWIDTH + hi], 1);
    }
}

// ---------------- kernel 2: per-row softplus stream + fused epilogue ----
// One block per row; the only pass over the big tensor. No fences, no
// cross-block coordination (R4 showed per-block gpu-scope fences cost ~18us).
__global__ void __launch_bounds__(256) row_kernel(const float* __restrict__ logits,
                                                  const long long* __restrict__ targets,
                                                  int V, int vec_ok) {
    const int r = blockIdx.x;
    const float* row = logits + (size_t)r * V;

    float acc0 = 0.0f, acc1 = 0.0f;
    if (vec_ok) {
        const float4* row4 = reinterpret_cast<const float4*>(row);
        const int n4 = V >> 2;
#pragma unroll 8
        for (int i = threadIdx.x; i < n4; i += 256) {
            float4 v = row4[i];
            acc0 += softplus_fast(v.x) + softplus_fast(v.z);
            acc1 += softplus_fast(v.y) + softplus_fast(v.w);
        }
    } else {
        for (int i = threadIdx.x; i < V; i += 256)
            acc0 += softplus_fast(row[i]);
    }
    float acc = acc0 + acc1;

    // block reduce
    __shared__ float warp_sums[8];
#pragma unroll
    for (int off = 16; off > 0; off >>= 1)
        acc += __shfl_xor_sync(0xFFFFFFFFu, acc, off);
    int lane = threadIdx.x & 31, wid = threadIdx.x >> 5;
    if (lane == 0) warp_sums[wid] = acc;
    __syncthreads();

    if (threadIdx.x == 0) {
        float S = 0.0f;
#pragma unroll
        for (int w = 0; w < 8; w++) S += warp_sums[w];

        long long t = targets[r];
        bool valid  = (t != -1);
        int ti = (t >= 0 && t < V) ? (int)t : 0;
        float spt = softplus_precise(row[ti]);
        float spi = softplus_precise(row[0]);

        float scale = fminf(1.0f / (S + 1e-6f), 1.0f);
        float rem   = fmaxf(1.0f - S * scale, 0.0f);
        float p_t   = spt * scale + ((t == 0) ? rem : 0.0f);
        float p_i   = spi * scale + rem;

        g_row_nll [r] = valid ? logf(fmaxf(p_t, 1e-10f)) : 0.0f;
        g_row_mask[r] = valid ? 1.0f : 0.0f;

        int c = 0x7fffffff;
#pragma unroll
        for (int d = 0; d < DEPTH; d++) {
            int h = g_hash[d * MAXN + r];
            c = min(c, g_hist[d * MAXWIDTH + h]);
        }
        float strength = tanhf((float)c * 0.1f);
        g_row_basis[r] = fmaxf(p_i - p_t + MARGIN, 0.0f) * strength;
    }
}

// ---------------- kernel 3: reduction + histogram restore ----------------
// Single 1024-thread block: deterministic fixed-order reduction, then
// restores g_hist to zero by replaying the saved hashes with atomicSub.
__global__ void __launch_bounds__(1024) final_kernel(float* __restrict__ out, int N) {
    float nll_sum = 0.0f, mask_sum = 0.0f, basis_sum = 0.0f;
    for (int n = threadIdx.x; n < N; n += 1024) {
        nll_sum   += g_row_nll[n];
        mask_sum  += g_row_mask[n];
        basis_sum += g_row_basis[n];
    }

    // restore histogram to zero (pipelined with the reduction's latency)
    for (int i = threadIdx.x; i < DEPTH * N; i += 1024) {
        int d = i / N, n = i - d * N;
        atomicSub(&g_hist[d * MAXWIDTH + g_hash[d * MAXN + n]], 1);
    }

    __shared__ float s0[32], s1[32], s2[32];
#pragma unroll
    for (int off = 16; off > 0; off >>= 1) {
        nll_sum   += __shfl_xor_sync(0xFFFFFFFFu, nll_sum,   off);
        mask_sum  += __shfl_xor_sync(0xFFFFFFFFu, mask_sum,  off);
        basis_sum += __shfl_xor_sync(0xFFFFFFFFu, basis_sum, off);
    }
    int lane = threadIdx.x & 31, wid = threadIdx.x >> 5;
    if (lane == 0) { s0[wid] = nll_sum; s1[wid] = mask_sum; s2[wid] = basis_sum; }
    __syncthreads();
    if (threadIdx.x == 0) {
        float a = 0, b = 0, c = 0;
#pragma unroll
        for (int w = 0; w < 32; w++) { a += s0[w]; b += s1[w]; c += s2[w]; }
        out[0] = -a / fmaxf(b, 1.0f) + BETA * (c / (float)N);
    }
}

extern "C" void kernel_launch(void* const* d_in, const int* in_sizes, int n_in,
                              void* d_out, int out_size) {
    // Resolve pointers by element count (robust to metadata ordering):
    //   salts: size == DEPTH; logits: largest; targets then inputs (relative order).
    const float*     logits  = nullptr;
    const long long* salts   = nullptr;
    const long long* tok[2]  = {nullptr, nullptr};
    int ntok_arrays = 0;
    long long logits_size = 0;
    int N = 0;

    for (int i = 0; i < n_in; i++) {
        long long sz = in_sizes[i];
        if (sz == DEPTH) {
            salts = (const long long*)d_in[i];
        } else if (sz > 1000000) {
            logits = (const float*)d_in[i];
            logits_size = sz;
        } else {
            if (ntok_arrays < 2) tok[ntok_arrays] = (const long long*)d_in[i];
            ntok_arrays++;
            N = (int)sz;
        }
    }
    const long long* targets = tok[0];
    const long long* inputs  = tok[1];

    int V = (N > 0) ? (int)(logits_size / N) : 0;
    long long width = 2LL * V;
    float* out = (float*)d_out;

    int vec_ok = (((uintptr_t)logits & 15) == 0) && (V % 4 == 0);

    hash_kernel<<<(N + 255) / 256, 256>>>(inputs, targets, salts, N, width);
    row_kernel<<<N, 256>>>(logits, targets, V, vec_ok);
    final_kernel<<<1, 1024>>>(out, N);
}

// round 6
// speedup vs baseline: 1.1835x; 1.0040x over previous
#include <cuda_runtime.h>
#include <cstdint>

#define DEPTH    3
#define MARGIN   0.1f
#define BETA     0.5f
#define MAXN     16384          // max tokens (B*T); actual 2048
#define MAXWIDTH 262144         // max 2*V; actual 64000

// ---- device scratch (allocation-free; zero-initialized at module load,
//      and restored to zero by final_kernel every invocation) ----
__device__ int   g_hist[DEPTH * MAXWIDTH];
__device__ int   g_hash[DEPTH * MAXN];
__device__ float g_row_nll  [MAXN];
__device__ float g_row_mask [MAXN];
__device__ float g_row_basis[MAXN];

// fast softplus for the bulk sum (MUFU EX2/LG2 path)
__device__ __forceinline__ float softplus_fast(float x) {
    float e = __expf(-fabsf(x));
    return fmaxf(x, 0.0f) + __logf(1.0f + e);
}
// precise softplus for the two per-row scalars feeding log()
__device__ __forceinline__ float softplus_precise(float x) {
    float e = expf(-fabsf(x));
    return fmaxf(x, 0.0f) + log1pf(e);
}

// ---------------- kernel 1: hash + bincount ----------------
// g_hist is guaranteed zero on entry (module load / previous final_kernel).
__global__ void hash_kernel(const long long* __restrict__ inputs,
                            const long long* __restrict__ targets,
                            const long long* __restrict__ salts,
                            int N, long long width) {
    int n = blockIdx.x * blockDim.x + threadIdx.x;
    if (n >= N) return;
    long long combined = inputs[n] * 31337LL + targets[n] * 2654435769LL;
#pragma unroll
    for (int d = 0; d < DEPTH; d++) {
        long long h = (combined + salts[d]) % width;
        if (h < 0) h += width;
        int hi = (int)h;
        g_hash[d * MAXN + n] = hi;
        atomicAdd(&g_hist[d * MAXWIDTH + hi], 1);
    }
}

// ---------------- kernel 2: per-row softplus stream + fused epilogue ----
// One block per row; the only pass over the big tensor. No fences, no
// cross-block coordination (R4 showed per-block gpu-scope fences cost ~18us).
__global__ void __launch_bounds__(256) row_kernel(const float* __restrict__ logits,
                                                  const long long* __restrict__ targets,
                                                  int V, int vec_ok) {
    const int r = blockIdx.x;
    const float* row = logits + (size_t)r * V;

    float acc0 = 0.0f, acc1 = 0.0f;
    if (vec_ok) {
        const float4* row4 = reinterpret_cast<const float4*>(row);
        const int n4 = V >> 2;
#pragma unroll 8
        for (int i = threadIdx.x; i < n4; i += 256) {
            float4 v = row4[i];
            acc0 += softplus_fast(v.x) + softplus_fast(v.z);
            acc1 += softplus_fast(v.y) + softplus_fast(v.w);
        }
    } else {
        for (int i = threadIdx.x; i < V; i += 256)
            acc0 += softplus_fast(row[i]);
    }
    float acc = acc0 + acc1;

    // block reduce
    __shared__ float warp_sums[8];
#pragma unroll
    for (int off = 16; off > 0; off >>= 1)
        acc += __shfl_xor_sync(0xFFFFFFFFu, acc, off);
    int lane = threadIdx.x & 31, wid = threadIdx.x >> 5;
    if (lane == 0) warp_sums[wid] = acc;
    __syncthreads();

    if (threadIdx.x == 0) {
        float S = 0.0f;
#pragma unroll
        for (int w = 0; w < 8; w++) S += warp_sums[w];

        long long t = targets[r];
        bool valid  = (t != -1);
        int ti = (t >= 0 && t < V) ? (int)t : 0;
        float spt = softplus_precise(row[ti]);
        float spi = softplus_precise(row[0]);

        float scale = fminf(1.0f / (S + 1e-6f), 1.0f);
        float rem   = fmaxf(1.0f - S * scale, 0.0f);
        float p_t   = spt * scale + ((t == 0) ? rem : 0.0f);
        float p_i   = spi * scale + rem;

        g_row_nll [r] = valid ? logf(fmaxf(p_t, 1e-10f)) : 0.0f;
        g_row_mask[r] = valid ? 1.0f : 0.0f;

        int c = 0x7fffffff;
#pragma unroll
        for (int d = 0; d < DEPTH; d++) {
            int h = g_hash[d * MAXN + r];
            c = min(c, g_hist[d * MAXWIDTH + h]);
        }
        float strength = tanhf((float)c * 0.1f);
        g_row_basis[r] = fmaxf(p_i - p_t + MARGIN, 0.0f) * strength;
    }
}

// ---------------- kernel 3: reduction + histogram restore ----------------
// Single 1024-thread block: deterministic fixed-order reduction, then
// restores g_hist to zero by replaying the saved hashes with atomicSub.
__global__ void __launch_bounds__(1024) final_kernel(float* __restrict__ out, int N) {
    float nll_sum = 0.0f, mask_sum = 0.0f, basis_sum = 0.0f;
    for (int n = threadIdx.x; n < N; n += 1024) {
        nll_sum   += g_row_nll[n];
        mask_sum  += g_row_mask[n];
        basis_sum += g_row_basis[n];
    }

    // restore histogram to zero (pipelined with the reduction's latency)
    for (int i = threadIdx.x; i < DEPTH * N; i += 1024) {
        int d = i / N, n = i - d * N;
        atomicSub(&g_hist[d * MAXWIDTH + g_hash[d * MAXN + n]], 1);
    }

    __shared__ float s0[32], s1[32], s2[32];
#pragma unroll
    for (int off = 16; off > 0; off >>= 1) {
        nll_sum   += __shfl_xor_sync(0xFFFFFFFFu, nll_sum,   off);
        mask_sum  += __shfl_xor_sync(0xFFFFFFFFu, mask_sum,  off);
        basis_sum += __shfl_xor_sync(0xFFFFFFFFu, basis_sum, off);
    }
    int lane = threadIdx.x & 31, wid = threadIdx.x >> 5;
    if (lane == 0) { s0[wid] = nll_sum; s1[wid] = mask_sum; s2[wid] = basis_sum; }
    __syncthreads();
    if (threadIdx.x == 0) {
        float a = 0, b = 0, c = 0;
#pragma unroll
        for (int w = 0; w < 32; w++) { a += s0[w]; b += s1[w]; c += s2[w]; }
        out[0] = -a / fmaxf(b, 1.0f) + BETA * (c / (float)N);
    }
}

extern "C" void kernel_launch(void* const* d_in, const int* in_sizes, int n_in,
                              void* d_out, int out_size) {
    // Resolve pointers by element count (robust to metadata ordering):
    //   salts: size == DEPTH; logits: largest; targets then inputs (relative order).
    const float*     logits  = nullptr;
    const long long* salts   = nullptr;
    const long long* tok[2]  = {nullptr, nullptr};
    int ntok_arrays = 0;
    long long logits_size = 0;
    int N = 0;

    for (int i = 0; i < n_in; i++) {
        long long sz = in_sizes[i];
        if (sz == DEPTH) {
            salts = (const long long*)d_in[i];
        } else if (sz > 1000000) {
            logits = (const float*)d_in[i];
            logits_size = sz;
        } else {
            if (ntok_arrays < 2) tok[ntok_arrays] = (const long long*)d_in[i];
            ntok_arrays++;
            N = (int)sz;
        }
    }
    const long long* targets = tok[0];
    const long long* inputs  = tok[1];

    int V = (N > 0) ? (int)(logits_size / N) : 0;
    long long width = 2LL * V;
    float* out = (float*)d_out;

    int vec_ok = (((uintptr_t)logits & 15) == 0) && (V % 4 == 0);

    hash_kernel<<<(N + 255) / 256, 256>>>(inputs, targets, salts, N, width);
    row_kernel<<<N, 256>>>(logits, targets, V, vec_ok);
    final_kernel<<<1, 1024>>>(out, N);
}

// round 7
// speedup vs baseline: 1.2235x; 1.0338x over previous
#include <cuda_runtime.h>
#include <cstdint>

#define DEPTH    3
#define MARGIN   0.1f
#define BETA     0.5f
#define MAXN     16384          // max tokens (B*T); actual 2048
#define MAXWIDTH 262144         // max 2*V; actual 64000

// ---- device scratch (allocation-free; zero-initialized at module load,
//      g_hist restored to zero by final_kernel every invocation) ----
__device__ int   g_hist[DEPTH * MAXWIDTH];
__device__ int   g_hash[DEPTH * MAXN];
__device__ float g_row_nll [MAXN];   // masked log(p_target)
__device__ float g_row_mask[MAXN];   // valid flag
__device__ float g_row_rerr[MAXN];   // max(p_idk - p_target + MARGIN, 0)

// fast softplus for the bulk sum (MUFU EX2/LG2 path)
__device__ __forceinline__ float softplus_fast(float x) {
    float e = __expf(-fabsf(x));
    return fmaxf(x, 0.0f) + __logf(1.0f + e);
}
// precise softplus for the two per-row scalars feeding log()
__device__ __forceinline__ float softplus_precise(float x) {
    float e = expf(-fabsf(x));
    return fmaxf(x, 0.0f) + log1pf(e);
}

// ---------------- kernel 1: stream + fused per-row epilogue + hashing ----
// Blocks [0, N): one block per row, stream V floats (only pass over the big
//   tensor), write per-row nll/mask/rerr. No histogram reads here.
// Blocks [N, N+hashBlocks): compute count-min hashes + histogram atomics,
//   overlapped with the stream (histogram is only read by final_kernel).
__global__ void __launch_bounds__(256) row_kernel(const float* __restrict__ logits,
                                                  const long long* __restrict__ targets,
                                                  const long long* __restrict__ inputs,
                                                  const long long* __restrict__ salts,
                                                  int N, int V, int vec_ok) {
    const int bid = blockIdx.x;

    if (bid >= N) {
        // ---- hash duty block ----
        int n = (bid - N) * 256 + threadIdx.x;
        if (n < N) {
            long long width = 2LL * V;
            long long combined = inputs[n] * 31337LL + targets[n] * 2654435769LL;
            long long cm = combined % width;          // one 64-bit mod
            if (cm < 0) cm += width;
            int cmi = (int)cm, w = (int)width;
#pragma unroll
            for (int d = 0; d < DEPTH; d++) {
                int sm = (int)(salts[d] % width);     // salts >= 0
                int h = cmi + sm;
                if (h >= w) h -= w;
                g_hash[d * MAXN + n] = h;
                atomicAdd(&g_hist[d * MAXWIDTH + h], 1);
            }
        }
        return;
    }

    // ---- streaming row block ----
    const int r = bid;
    const float* row = logits + (size_t)r * V;

    float acc = 0.0f;
    if (vec_ok) {
        const float4* row4 = reinterpret_cast<const float4*>(row);
        const int n4 = V >> 2;
#pragma unroll 4
        for (int i = threadIdx.x; i < n4; i += 256) {
            float4 v = row4[i];
            acc += softplus_fast(v.x);
            acc += softplus_fast(v.y);
            acc += softplus_fast(v.z);
            acc += softplus_fast(v.w);
        }
    } else {
        for (int i = threadIdx.x; i < V; i += 256)
            acc += softplus_fast(row[i]);
    }

    // block reduce
    __shared__ float warp_sums[8];
#pragma unroll
    for (int off = 16; off > 0; off >>= 1)
        acc += __shfl_xor_sync(0xFFFFFFFFu, acc, off);
    int lane = threadIdx.x & 31, wid = threadIdx.x >> 5;
    if (lane == 0) warp_sums[wid] = acc;
    __syncthreads();

    if (threadIdx.x == 0) {
        float S = 0.0f;
#pragma unroll
        for (int w = 0; w < 8; w++) S += warp_sums[w];

        long long t = targets[r];
        bool valid  = (t != -1);
        int ti = (t >= 0 && t < V) ? (int)t : 0;
        float spt = softplus_precise(row[ti]);
        float spi = softplus_precise(row[0]);

        float scale = fminf(1.0f / (S + 1e-6f), 1.0f);
        float rem   = fmaxf(1.0f - S * scale, 0.0f);
        float p_t   = spt * scale + ((t == 0) ? rem : 0.0f);
        float p_i   = spi * scale + rem;

        g_row_nll [r] = valid ? logf(fmaxf(p_t, 1e-10f)) : 0.0f;
        g_row_mask[r] = valid ? 1.0f : 0.0f;
        g_row_rerr[r] = fmaxf(p_i - p_t + MARGIN, 0.0f);
    }
}

// ---------------- kernel 2: count-min query + reduction + restore --------
// Single 1024-thread block. Histogram complete (built by previous launch).
__global__ void __launch_bounds__(1024) final_kernel(float* __restrict__ out, int N) {
    float nll_sum = 0.0f, mask_sum = 0.0f, basis_sum = 0.0f;

    for (int n = threadIdx.x; n < N; n += 1024) {
        nll_sum  += g_row_nll[n];
        mask_sum += g_row_mask[n];

        int h0 = g_hash[0 * MAXN + n];
        int h1 = g_hash[1 * MAXN + n];
        int h2 = g_hash[2 * MAXN + n];
        int c0 = g_hist[0 * MAXWIDTH + h0];
        int c1 = g_hist[1 * MAXWIDTH + h1];
        int c2 = g_hist[2 * MAXWIDTH + h2];
        int c  = min(c0, min(c1, c2));
        basis_sum += g_row_rerr[n] * tanhf((float)c * 0.1f);
    }

    // restore histogram to zero by replaying hashes (graph-replay safe)
    for (int i = threadIdx.x; i < DEPTH * N; i += 1024) {
        int d = i / N, n = i - d * N;
        atomicSub(&g_hist[d * MAXWIDTH + g_hash[d * MAXN + n]], 1);
    }

    __shared__ float s0[32], s1[32], s2[32];
#pragma unroll
    for (int off = 16; off > 0; off >>= 1) {
        nll_sum   += __shfl_xor_sync(0xFFFFFFFFu, nll_sum,   off);
        mask_sum  += __shfl_xor_sync(0xFFFFFFFFu, mask_sum,  off);
        basis_sum += __shfl_xor_sync(0xFFFFFFFFu, basis_sum, off);
    }
    int lane = threadIdx.x & 31, wid = threadIdx.x >> 5;
    if (lane == 0) { s0[wid] = nll_sum; s1[wid] = mask_sum; s2[wid] = basis_sum; }
    __syncthreads();
    if (threadIdx.x == 0) {
        float a = 0, b = 0, c = 0;
#pragma unroll
        for (int w = 0; w < 32; w++) { a += s0[w]; b += s1[w]; c += s2[w]; }
        out[0] = -a / fmaxf(b, 1.0f) + BETA * (c / (float)N);
    }
}

extern "C" void kernel_launch(void* const* d_in, const int* in_sizes, int n_in,
                              void* d_out, int out_size) {
    // Resolve pointers by element count (robust to metadata ordering):
    //   salts: size == DEPTH; logits: largest; targets then inputs (relative order).
    const float*     logits  = nullptr;
    const long long* salts   = nullptr;
    const long long* tok[2]  = {nullptr, nullptr};
    int ntok_arrays = 0;
    long long logits_size = 0;
    int N = 0;

    for (int i = 0; i < n_in; i++) {
        long long sz = in_sizes[i];
        if (sz == DEPTH) {
            salts = (const long long*)d_in[i];
        } else if (sz > 1000000) {
            logits = (const float*)d_in[i];
            logits_size = sz;
        } else {
            if (ntok_arrays < 2) tok[ntok_arrays] = (const long long*)d_in[i];
            ntok_arrays++;
            N = (int)sz;
        }
    }
    const long long* targets = tok[0];
    const long long* inputs  = tok[1];

    int V = (N > 0) ? (int)(logits_size / N) : 0;
    float* out = (float*)d_out;

    int vec_ok = (((uintptr_t)logits & 15) == 0) && (V % 4 == 0);
    int hash_blocks = (N + 255) / 256;

    row_kernel<<<N + hash_blocks, 256>>>(logits, targets, inputs, salts, N, V, vec_ok);
    final_kernel<<<1, 1024>>>(out, N);
}